// round 6
// baseline (speedup 1.0000x reference)
#include <cuda_runtime.h>
#include <cstdint>

#define BS   4
#define SEQ  128
#define DIM  768
#define HID  768
#define NOUT 2
#define MROWS (BS * SEQ)                    // 512
#define KSPLIT 384                          // K per split-K half

// ---------------- device scratch (no allocation allowed) -------------------
__device__ float g_ar[MROWS * DIM];         // tf32-rounded a
__device__ float g_br[MROWS * DIM];         // tf32-rounded b
__device__ float g_W1r[2 * DIM * HID];      // tf32-rounded W1
__device__ float g_ha[MROWS * HID];         // partial: a @ W1[:D], k-half 0
__device__ float g_hb[MROWS * HID];         // partial: b @ W1[D:] + b1, k-half 0
__device__ float g_ha2[MROWS * HID];        // partial k-half 1
__device__ float g_hb2[MROWS * HID];        // partial k-half 1

// ---------------------------------------------------------------------------
__device__ __forceinline__ uint32_t smem_u32(const void* p) {
    uint32_t a;
    asm("{ .reg .u64 t; cvta.to.shared.u64 t, %1; cvt.u32.u64 %0, t; }"
        : "=r"(a) : "l"(p));
    return a;
}

__device__ __forceinline__ void cp_async16(uint32_t saddr, const void* gptr) {
    asm volatile("cp.async.cg.shared.global [%0], [%1], 16;"
                 :: "r"(saddr), "l"(gptr) : "memory");
}
__device__ __forceinline__ void cp_commit() {
    asm volatile("cp.async.commit_group;" ::: "memory");
}
template <int N>
__device__ __forceinline__ void cp_wait() {
    asm volatile("cp.async.wait_group %0;" :: "n"(N) : "memory");
}

__device__ __forceinline__ float rnd_tf32(float x) {
    uint32_t u;
    asm("cvt.rna.tf32.f32 %0, %1;" : "=r"(u) : "f"(x));
    return __uint_as_float(u);
}

__device__ __forceinline__ void mma_tf32(float* c, const uint32_t* a,
                                         const uint32_t* b) {
    asm volatile(
        "mma.sync.aligned.m16n8k8.row.col.f32.tf32.tf32.f32 "
        "{%0,%1,%2,%3}, {%4,%5,%6,%7}, {%8,%9}, {%0,%1,%2,%3};"
        : "+f"(c[0]), "+f"(c[1]), "+f"(c[2]), "+f"(c[3])
        : "r"(a[0]), "r"(a[1]), "r"(a[2]), "r"(a[3]), "r"(b[0]), "r"(b[1]));
}

// ---------------------------------------------------------------------------
// Kernel 0: round a, b, W1 to tf32-exact fp32 (single fused elementwise pass).
// float4 ranges: a [0,98304), b [98304,196608), W1 [196608,491520).
// ---------------------------------------------------------------------------
__global__ __launch_bounds__(256) void prep_kernel(
    const float* __restrict__ a, const float* __restrict__ b,
    const float* __restrict__ W1)
{
    int i = blockIdx.x * 256 + threadIdx.x;
    const float4* src;
    float4* dst;
    int off;
    if (i < 98304)        { src = (const float4*)a;  dst = (float4*)g_ar;  off = i; }
    else if (i < 196608)  { src = (const float4*)b;  dst = (float4*)g_br;  off = i - 98304; }
    else                  { src = (const float4*)W1; dst = (float4*)g_W1r; off = i - 196608; }
    float4 v = src[off];
    v.x = rnd_tf32(v.x); v.y = rnd_tf32(v.y);
    v.z = rnd_tf32(v.z); v.w = rnd_tf32(v.w);
    dst[off] = v;
}

// ---------------------------------------------------------------------------
// Kernel 1: projection GEMM via mma.sync tf32, split-K=2, BK=32,
// 3-stage cp.async pipeline with ONE __syncthreads per iteration.
// blockIdx.z: bit0 = z (a/b), bit1 = k-split half.
// CTA tile 64m x 64n, 256 threads (8 warps, warp tile 32x16).
// Grid (12, 8, 4) = 384 CTAs. Dynamic smem 55296 B.
// ---------------------------------------------------------------------------
#define ALD 36
#define BLD 72
#define STG_A (64 * ALD)                 // 2304 floats per A stage
#define STG_B (32 * BLD)                 // 2304 floats per B stage
#define PROJ_SMEM_BYTES (3 * (STG_A + STG_B) * 4)   // 55296

__global__ __launch_bounds__(256) void proj_tc(const float* __restrict__ b1)
{
    extern __shared__ float psm[];
    float* const Asm = psm;                    // 3 stages of A
    float* const Bsm = psm + 3 * STG_A;        // 3 stages of B

    const int tid = threadIdx.x;
    const int wid = tid >> 5;
    const int lane = tid & 31;
    const int r = lane >> 2;            // 0..7
    const int c = lane & 3;             // 0..3
    const int wm = (wid >> 2) * 32;     // warp m base {0,32}
    const int wn = (wid & 3) * 16;      // warp n base {0,16,32,48}

    const int n0 = blockIdx.x * 64;
    const int m0 = blockIdx.y * 64;
    const int z  = blockIdx.z & 1;
    const int kh = blockIdx.z >> 1;
    const int kbase = kh * KSPLIT;

    const float* __restrict__ X = z ? g_br : g_ar;
    const float* __restrict__ W = g_W1r + (size_t)z * DIM * HID;

    const uint32_t sA = smem_u32(Asm);
    const uint32_t sB = smem_u32(Bsm);

    // per-chunk loads: A 512 float4 (2/thread), B 512 float4 (2/thread)
    auto ldchunk = [&](int chunk, int s) {
        const int k0 = kbase + chunk * 32;
        #pragma unroll
        for (int i = 0; i < 2; i++) {
            int f = i * 256 + tid;
            int row = f >> 3, kc = (f & 7) * 4;
            cp_async16(sA + (uint32_t)(s * STG_A + row * ALD + kc) * 4,
                       X + (size_t)(m0 + row) * DIM + k0 + kc);
        }
        #pragma unroll
        for (int i = 0; i < 2; i++) {
            int f = i * 256 + tid;
            int kr = f >> 4, nc = (f & 15) * 4;
            cp_async16(sB + (uint32_t)(s * STG_B + kr * BLD + nc) * 4,
                       W + (size_t)(k0 + kr) * HID + n0 + nc);
        }
        cp_commit();
    };

    float acc[2][2][4] = {};

    ldchunk(0, 0);
    ldchunk(1, 1);

    for (int chunk = 0; chunk < 12; chunk++) {
        const int s = chunk % 3;
        if (chunk < 11) cp_wait<1>(); else cp_wait<0>();
        __syncthreads();                 // publish chunk data + WAR safety

        const uint32_t* Ab = (const uint32_t*)(Asm + s * STG_A);
        const uint32_t* Bb = (const uint32_t*)(Bsm + s * STG_B);
        #pragma unroll
        for (int ks = 0; ks < 4; ks++) {
            const int kb = ks * 8;
            uint32_t af[2][4];
            #pragma unroll
            for (int mt = 0; mt < 2; mt++) {
                const uint32_t* ap = Ab + (wm + mt * 16 + r) * ALD + kb + c;
                af[mt][0] = ap[0];
                af[mt][1] = ap[8 * ALD];
                af[mt][2] = ap[4];
                af[mt][3] = ap[8 * ALD + 4];
            }
            uint32_t bf[2][2];
            #pragma unroll
            for (int nt = 0; nt < 2; nt++) {
                const uint32_t* bp = Bb + (kb + c) * BLD + wn + nt * 8 + r;
                bf[nt][0] = bp[0];
                bf[nt][1] = bp[4 * BLD];
            }
            #pragma unroll
            for (int nt = 0; nt < 2; nt++)
                #pragma unroll
                for (int mt = 0; mt < 2; mt++)
                    mma_tf32(acc[mt][nt], af[mt], bf[nt]);
        }

        if (chunk + 2 < 12) ldchunk(chunk + 2, (chunk + 2) % 3);
    }

    // epilogue: write per-split partial (+ b1 once, on z=1 k-half 0)
    float* __restrict__ outp = z ? (kh ? g_hb2 : g_hb) : (kh ? g_ha2 : g_ha);
    const bool addb = (z == 1) && (kh == 0);
    #pragma unroll
    for (int mt = 0; mt < 2; mt++) {
        #pragma unroll
        for (int nt = 0; nt < 2; nt++) {
            int m = m0 + wm + mt * 16 + r;
            int n = n0 + wn + nt * 8 + c * 2;
            float2 v0 = make_float2(acc[mt][nt][0], acc[mt][nt][1]);
            float2 v1 = make_float2(acc[mt][nt][2], acc[mt][nt][3]);
            if (addb) {
                float2 bb = *(const float2*)&b1[n];
                v0.x += bb.x; v0.y += bb.y;
                v1.x += bb.x; v1.y += bb.y;
            }
            *(float2*)&outp[(size_t)m * HID + n] = v0;
            *(float2*)&outp[(size_t)(m + 8) * HID + n] = v1;
        }
    }
}

// ---------------------------------------------------------------------------
// Kernel 2: pairwise relu + reduce to O=2, fused final output.
// Tile 32s x 16t per CTA; 256 threads = 2 groups of 128, each group covers
// one H-half (384), 2x2 pairs per thread; smem reduction merges halves,
// adds b2, writes final out. Sums the split-K proj partials during fill.
// Grid (SEQ/16, SEQ/32, BS) = (8, 4, 4) = 128 CTAs.
// ---------------------------------------------------------------------------
#define HC 64
__global__ __launch_bounds__(256) void pair_kernel(
    const float* __restrict__ W2, const float* __restrict__ b2,
    float* __restrict__ out)
{
    const int tt = blockIdx.x;              // t tile (16 wide)
    const int st = blockIdx.y;              // s tile (32 wide)
    const int batch = blockIdx.z;

    __shared__ float sha[2][32][68];        // [g][s][h], pad 68 (f4-aligned)
    __shared__ float shB[2][16][65];        // [g][t][h], pad 65
    __shared__ float sw[2][HC * 2];
    __shared__ float red[8][128];

    const int tid = threadIdx.x;
    const int g  = tid >> 7;                // h-half group
    const int lt = tid & 127;
    const int sq = lt >> 3;                 // 0..15 (s pair)
    const int tq = lt & 7;                  // 0..7  (t pair)
    const int h0base = g * (HID / 2);

    const size_t rowS = (size_t)(batch * SEQ + st * 32) * HID;
    const size_t rowT = (size_t)(batch * SEQ + tt * 16) * HID;
    const float* __restrict__ hap  = g_ha  + rowS;
    const float* __restrict__ hap2 = g_ha2 + rowS;
    const float* __restrict__ hbp  = g_hb  + rowT;
    const float* __restrict__ hbp2 = g_hb2 + rowT;

    float acc[2][2][2] = {};

    for (int hc = 0; hc < HID / 2; hc += HC) {
        const int h0 = h0base + hc;

        // fill sha: 32 rows x 64 h, 4 float4 per thread (coalesced)
        #pragma unroll
        for (int q = 0; q < 4; q++) {
            int f = q * 128 + lt;
            int row = f >> 4, col = (f & 15) * 4;
            float4 u  = *(const float4*)&hap [(size_t)row * HID + h0 + col];
            float4 u2 = *(const float4*)&hap2[(size_t)row * HID + h0 + col];
            u.x += u2.x; u.y += u2.y; u.z += u2.z; u.w += u2.w;
            *(float4*)&sha[g][row][col] = u;
        }
        // fill shB: 16 rows x 64 h, 2 float4 per thread (scalar STS, pad 65)
        #pragma unroll
        for (int q = 0; q < 2; q++) {
            int f = q * 128 + lt;
            int row = f >> 4, col = (f & 15) * 4;
            float4 v  = *(const float4*)&hbp [(size_t)row * HID + h0 + col];
            float4 v2 = *(const float4*)&hbp2[(size_t)row * HID + h0 + col];
            v.x += v2.x; v.y += v2.y; v.z += v2.z; v.w += v2.w;
            shB[g][row][col + 0] = v.x;
            shB[g][row][col + 1] = v.y;
            shB[g][row][col + 2] = v.z;
            shB[g][row][col + 3] = v.w;
        }
        if (lt < 32)
            *(float4*)&sw[g][lt * 4] = *(const float4*)&W2[h0 * 2 + lt * 4];
        __syncthreads();

        #pragma unroll 16
        for (int h = 0; h < HC; h++) {
            float a0 = sha[g][sq * 2][h];
            float a1 = sha[g][sq * 2 + 1][h];
            float b0 = shB[g][tq * 2][h];
            float b1v = shB[g][tq * 2 + 1][h];
            float2 wv = *(const float2*)&sw[g][2 * h];
            float r;
            r = fmaxf(a0 + b0,  0.f); acc[0][0][0] += r * wv.x; acc[0][0][1] += r * wv.y;
            r = fmaxf(a0 + b1v, 0.f); acc[0][1][0] += r * wv.x; acc[0][1][1] += r * wv.y;
            r = fmaxf(a1 + b0,  0.f); acc[1][0][0] += r * wv.x; acc[1][0][1] += r * wv.y;
            r = fmaxf(a1 + b1v, 0.f); acc[1][1][0] += r * wv.x; acc[1][1][1] += r * wv.y;
        }
        __syncthreads();
    }

    // merge the two h-halves via smem, add b2, write final output
    const float* af = (const float*)acc;
    if (g == 0) {
        #pragma unroll
        for (int k = 0; k < 8; k++) red[k][lt] = af[k];
    }
    __syncthreads();
    if (g == 1) {
        float c0 = b2[0], c1 = b2[1];
        #pragma unroll
        for (int i = 0; i < 2; i++) {
            int s = st * 32 + sq * 2 + i;
            int t = tt * 16 + tq * 2;
            float4 v;
            v.x = acc[i][0][0] + red[i * 4 + 0][lt] + c0;
            v.y = acc[i][0][1] + red[i * 4 + 1][lt] + c1;
            v.z = acc[i][1][0] + red[i * 4 + 2][lt] + c0;
            v.w = acc[i][1][1] + red[i * 4 + 3][lt] + c1;
            *(float4*)&out[(((size_t)batch * SEQ + s) * SEQ + t) * NOUT] = v;
        }
    }
}

// ---------------------------------------------------------------------------
extern "C" void kernel_launch(void* const* d_in, const int* in_sizes, int n_in,
                              void* d_out, int out_size)
{
    const float* a  = (const float*)d_in[0];
    const float* b  = (const float*)d_in[1];
    const float* W1 = (const float*)d_in[2];
    const float* b1 = (const float*)d_in[3];
    const float* W2 = (const float*)d_in[4];
    const float* b2 = (const float*)d_in[5];
    float* out = (float*)d_out;

    cudaFuncSetAttribute(proj_tc, cudaFuncAttributeMaxDynamicSharedMemorySize,
                         PROJ_SMEM_BYTES);

    prep_kernel<<<1920, 256>>>(a, b, W1);
    proj_tc<<<dim3(HID / 64, MROWS / 64, 4), 256, PROJ_SMEM_BYTES>>>(b1);
    pair_kernel<<<dim3(SEQ / 16, SEQ / 32, BS), 256>>>(W2, b2, out);
}

// round 7
// speedup vs baseline: 1.0125x; 1.0125x over previous
#include <cuda_runtime.h>
#include <cstdint>

#define BS   4
#define SEQ  128
#define DIM  768
#define HID  768
#define NOUT 2
#define MROWS (BS * SEQ)                    // 512
#define KSPLIT 384                          // K per split-K half

// ---------------- device scratch (no allocation allowed) -------------------
__device__ float g_ar[MROWS * DIM];         // tf32-rounded a
__device__ float g_br[MROWS * DIM];         // tf32-rounded b
__device__ float g_W1r[2 * DIM * HID];      // tf32-rounded W1
__device__ float g_ha[MROWS * HID];         // partial: a @ W1[:D], k-half 0
__device__ float g_hb[MROWS * HID];         // partial: b @ W1[D:] + b1, k-half 0
__device__ float g_ha2[MROWS * HID];        // partial k-half 1
__device__ float g_hb2[MROWS * HID];        // partial k-half 1

// ---------------------------------------------------------------------------
__device__ __forceinline__ uint32_t smem_u32(const void* p) {
    uint32_t a;
    asm("{ .reg .u64 t; cvta.to.shared.u64 t, %1; cvt.u32.u64 %0, t; }"
        : "=r"(a) : "l"(p));
    return a;
}

__device__ __forceinline__ void cp_async16(uint32_t saddr, const void* gptr) {
    asm volatile("cp.async.cg.shared.global [%0], [%1], 16;"
                 :: "r"(saddr), "l"(gptr) : "memory");
}
__device__ __forceinline__ void cp_commit() {
    asm volatile("cp.async.commit_group;" ::: "memory");
}
template <int N>
__device__ __forceinline__ void cp_wait() {
    asm volatile("cp.async.wait_group %0;" :: "n"(N) : "memory");
}

__device__ __forceinline__ float rnd_tf32(float x) {
    uint32_t u;
    asm("cvt.rna.tf32.f32 %0, %1;" : "=r"(u) : "f"(x));
    return __uint_as_float(u);
}

__device__ __forceinline__ void mma_tf32(float* c, const uint32_t* a,
                                         const uint32_t* b) {
    asm volatile(
        "mma.sync.aligned.m16n8k8.row.col.f32.tf32.tf32.f32 "
        "{%0,%1,%2,%3}, {%4,%5,%6,%7}, {%8,%9}, {%0,%1,%2,%3};"
        : "+f"(c[0]), "+f"(c[1]), "+f"(c[2]), "+f"(c[3])
        : "r"(a[0]), "r"(a[1]), "r"(a[2]), "r"(a[3]), "r"(b[0]), "r"(b[1]));
}

// ---------------------------------------------------------------------------
// Kernel 0: round a, b, W1 to tf32-exact fp32.
// Each block owns a 1024-float4 window (all segment boundaries are multiples
// of 1024 f4: a ends at 98304, b at 196608, W1 at 491520). Each thread does
// 4 batched coalesced LDG.128 (MLP=4), 16 cvt, 4 STG.128.
// ---------------------------------------------------------------------------
__global__ __launch_bounds__(256) void prep_kernel(
    const float* __restrict__ a, const float* __restrict__ b,
    const float* __restrict__ W1)
{
    const int w0 = blockIdx.x * 1024;           // window base (float4)
    const float4* src;
    float4* dst;
    int off;
    if (w0 < 98304)        { src = (const float4*)a;  dst = (float4*)g_ar;  off = w0; }
    else if (w0 < 196608)  { src = (const float4*)b;  dst = (float4*)g_br;  off = w0 - 98304; }
    else                   { src = (const float4*)W1; dst = (float4*)g_W1r; off = w0 - 196608; }
    src += off + threadIdx.x;
    dst += off + threadIdx.x;

    float4 v[4];
    #pragma unroll
    for (int i = 0; i < 4; i++) v[i] = src[i * 256];
    #pragma unroll
    for (int i = 0; i < 4; i++) {
        v[i].x = rnd_tf32(v[i].x); v[i].y = rnd_tf32(v[i].y);
        v[i].z = rnd_tf32(v[i].z); v[i].w = rnd_tf32(v[i].w);
    }
    #pragma unroll
    for (int i = 0; i < 4; i++) dst[i * 256] = v[i];
}

// ---------------------------------------------------------------------------
// Kernel 1: projection GEMM via mma.sync tf32, split-K=2, BK=32.
// CTA tile 64m x 64n, 128 threads = 4 warps (2x2), warp tile 32x32
// (8 HMMA per 16 LDS per k-step). 3-stage cp.async pipeline, prefetch
// issued BEFORE compute. Grid (12, 8, 4) = 384 CTAs. Dyn smem 55296 B.
// ---------------------------------------------------------------------------
#define ALD 36
#define BLD 72
#define STG_A (64 * ALD)
#define STG_B (32 * BLD)
#define PROJ_SMEM_BYTES (3 * (STG_A + STG_B) * 4)   // 55296

__global__ __launch_bounds__(128) void proj_tc(const float* __restrict__ b1)
{
    extern __shared__ float psm[];
    float* const Asm = psm;
    float* const Bsm = psm + 3 * STG_A;

    const int tid = threadIdx.x;
    const int wid = tid >> 5;
    const int lane = tid & 31;
    const int r = lane >> 2;            // 0..7
    const int c = lane & 3;             // 0..3
    const int wm = (wid >> 1) * 32;     // warp m base {0,32}
    const int wn = (wid & 1) * 32;      // warp n base {0,32}

    const int n0 = blockIdx.x * 64;
    const int m0 = blockIdx.y * 64;
    const int z  = blockIdx.z & 1;
    const int kh = blockIdx.z >> 1;
    const int kbase = kh * KSPLIT;

    const float* __restrict__ X = z ? g_br : g_ar;
    const float* __restrict__ W = g_W1r + (size_t)z * DIM * HID;

    const uint32_t sA = smem_u32(Asm);
    const uint32_t sB = smem_u32(Bsm);

    // per-chunk loads: A 64x32 = 512 f4 (4/thread), B 32x64 = 512 f4 (4/thread)
    auto ldchunk = [&](int chunk, int s) {
        const int k0 = kbase + chunk * 32;
        #pragma unroll
        for (int i = 0; i < 4; i++) {
            int f = i * 128 + tid;
            int row = f >> 3, kc = (f & 7) * 4;
            cp_async16(sA + (uint32_t)(s * STG_A + row * ALD + kc) * 4,
                       X + (size_t)(m0 + row) * DIM + k0 + kc);
        }
        #pragma unroll
        for (int i = 0; i < 4; i++) {
            int f = i * 128 + tid;
            int kr = f >> 4, nc = (f & 15) * 4;
            cp_async16(sB + (uint32_t)(s * STG_B + kr * BLD + nc) * 4,
                       W + (size_t)(k0 + kr) * HID + n0 + nc);
        }
        cp_commit();
    };

    float acc[2][4][4] = {};

    ldchunk(0, 0);
    ldchunk(1, 1);

    for (int chunk = 0; chunk < 12; chunk++) {
        const int s = chunk % 3;
        if (chunk < 11) cp_wait<1>(); else cp_wait<0>();
        __syncthreads();                       // publish stage s + WAR safety

        if (chunk + 2 < 12) ldchunk(chunk + 2, (chunk + 2) % 3);  // early issue

        const uint32_t* Ab = (const uint32_t*)(Asm + s * STG_A);
        const uint32_t* Bb = (const uint32_t*)(Bsm + s * STG_B);
        #pragma unroll
        for (int ks = 0; ks < 4; ks++) {
            const int kb = ks * 8;
            uint32_t af[2][4];
            #pragma unroll
            for (int mt = 0; mt < 2; mt++) {
                const uint32_t* ap = Ab + (wm + mt * 16 + r) * ALD + kb + c;
                af[mt][0] = ap[0];
                af[mt][1] = ap[8 * ALD];
                af[mt][2] = ap[4];
                af[mt][3] = ap[8 * ALD + 4];
            }
            uint32_t bf[4][2];
            #pragma unroll
            for (int nt = 0; nt < 4; nt++) {
                const uint32_t* bp = Bb + (kb + c) * BLD + wn + nt * 8 + r;
                bf[nt][0] = bp[0];
                bf[nt][1] = bp[4 * BLD];
            }
            #pragma unroll
            for (int nt = 0; nt < 4; nt++)
                #pragma unroll
                for (int mt = 0; mt < 2; mt++)
                    mma_tf32(acc[mt][nt], af[mt], bf[nt]);
        }
    }

    // epilogue: write per-split partial (+ b1 once, on z=1 k-half 0)
    float* __restrict__ outp = z ? (kh ? g_hb2 : g_hb) : (kh ? g_ha2 : g_ha);
    const bool addb = (z == 1) && (kh == 0);
    #pragma unroll
    for (int mt = 0; mt < 2; mt++) {
        #pragma unroll
        for (int nt = 0; nt < 4; nt++) {
            int m = m0 + wm + mt * 16 + r;
            int n = n0 + wn + nt * 8 + c * 2;
            float2 v0 = make_float2(acc[mt][nt][0], acc[mt][nt][1]);
            float2 v1 = make_float2(acc[mt][nt][2], acc[mt][nt][3]);
            if (addb) {
                float2 bb = *(const float2*)&b1[n];
                v0.x += bb.x; v0.y += bb.y;
                v1.x += bb.x; v1.y += bb.y;
            }
            *(float2*)&outp[(size_t)m * HID + n] = v0;
            *(float2*)&outp[(size_t)(m + 8) * HID + n] = v1;
        }
    }
}

// ---------------------------------------------------------------------------
// Kernel 2: pairwise relu + reduce to O=2, fused final output (unchanged).
// Grid (8, 4, 4) = 128 CTAs, 256 threads = 2 h-half groups of 128.
// ---------------------------------------------------------------------------
#define HC 64
__global__ __launch_bounds__(256) void pair_kernel(
    const float* __restrict__ W2, const float* __restrict__ b2,
    float* __restrict__ out)
{
    const int tt = blockIdx.x;
    const int st = blockIdx.y;
    const int batch = blockIdx.z;

    __shared__ float sha[2][32][68];
    __shared__ float shB[2][16][65];
    __shared__ float sw[2][HC * 2];
    __shared__ float red[8][128];

    const int tid = threadIdx.x;
    const int g  = tid >> 7;
    const int lt = tid & 127;
    const int sq = lt >> 3;
    const int tq = lt & 7;
    const int h0base = g * (HID / 2);

    const size_t rowS = (size_t)(batch * SEQ + st * 32) * HID;
    const size_t rowT = (size_t)(batch * SEQ + tt * 16) * HID;
    const float* __restrict__ hap  = g_ha  + rowS;
    const float* __restrict__ hap2 = g_ha2 + rowS;
    const float* __restrict__ hbp  = g_hb  + rowT;
    const float* __restrict__ hbp2 = g_hb2 + rowT;

    float acc[2][2][2] = {};

    for (int hc = 0; hc < HID / 2; hc += HC) {
        const int h0 = h0base + hc;

        #pragma unroll
        for (int q = 0; q < 4; q++) {
            int f = q * 128 + lt;
            int row = f >> 4, col = (f & 15) * 4;
            float4 u  = *(const float4*)&hap [(size_t)row * HID + h0 + col];
            float4 u2 = *(const float4*)&hap2[(size_t)row * HID + h0 + col];
            u.x += u2.x; u.y += u2.y; u.z += u2.z; u.w += u2.w;
            *(float4*)&sha[g][row][col] = u;
        }
        #pragma unroll
        for (int q = 0; q < 2; q++) {
            int f = q * 128 + lt;
            int row = f >> 4, col = (f & 15) * 4;
            float4 v  = *(const float4*)&hbp [(size_t)row * HID + h0 + col];
            float4 v2 = *(const float4*)&hbp2[(size_t)row * HID + h0 + col];
            v.x += v2.x; v.y += v2.y; v.z += v2.z; v.w += v2.w;
            shB[g][row][col + 0] = v.x;
            shB[g][row][col + 1] = v.y;
            shB[g][row][col + 2] = v.z;
            shB[g][row][col + 3] = v.w;
        }
        if (lt < 32)
            *(float4*)&sw[g][lt * 4] = *(const float4*)&W2[h0 * 2 + lt * 4];
        __syncthreads();

        #pragma unroll 16
        for (int h = 0; h < HC; h++) {
            float a0 = sha[g][sq * 2][h];
            float a1 = sha[g][sq * 2 + 1][h];
            float b0 = shB[g][tq * 2][h];
            float b1v = shB[g][tq * 2 + 1][h];
            float2 wv = *(const float2*)&sw[g][2 * h];
            float r;
            r = fmaxf(a0 + b0,  0.f); acc[0][0][0] += r * wv.x; acc[0][0][1] += r * wv.y;
            r = fmaxf(a0 + b1v, 0.f); acc[0][1][0] += r * wv.x; acc[0][1][1] += r * wv.y;
            r = fmaxf(a1 + b0,  0.f); acc[1][0][0] += r * wv.x; acc[1][0][1] += r * wv.y;
            r = fmaxf(a1 + b1v, 0.f); acc[1][1][0] += r * wv.x; acc[1][1][1] += r * wv.y;
        }
        __syncthreads();
    }

    const float* af = (const float*)acc;
    if (g == 0) {
        #pragma unroll
        for (int k = 0; k < 8; k++) red[k][lt] = af[k];
    }
    __syncthreads();
    if (g == 1) {
        float c0 = b2[0], c1 = b2[1];
        #pragma unroll
        for (int i = 0; i < 2; i++) {
            int s = st * 32 + sq * 2 + i;
            int t = tt * 16 + tq * 2;
            float4 v;
            v.x = acc[i][0][0] + red[i * 4 + 0][lt] + c0;
            v.y = acc[i][0][1] + red[i * 4 + 1][lt] + c1;
            v.z = acc[i][1][0] + red[i * 4 + 2][lt] + c0;
            v.w = acc[i][1][1] + red[i * 4 + 3][lt] + c1;
            *(float4*)&out[(((size_t)batch * SEQ + s) * SEQ + t) * NOUT] = v;
        }
    }
}

// ---------------------------------------------------------------------------
extern "C" void kernel_launch(void* const* d_in, const int* in_sizes, int n_in,
                              void* d_out, int out_size)
{
    const float* a  = (const float*)d_in[0];
    const float* b  = (const float*)d_in[1];
    const float* W1 = (const float*)d_in[2];
    const float* b1 = (const float*)d_in[3];
    const float* W2 = (const float*)d_in[4];
    const float* b2 = (const float*)d_in[5];
    float* out = (float*)d_out;

    cudaFuncSetAttribute(proj_tc, cudaFuncAttributeMaxDynamicSharedMemorySize,
                         PROJ_SMEM_BYTES);

    prep_kernel<<<480, 256>>>(a, b, W1);
    proj_tc<<<dim3(HID / 64, MROWS / 64, 4), 128, PROJ_SMEM_BYTES>>>(b1);
    pair_kernel<<<dim3(SEQ / 16, SEQ / 32, BS), 256>>>(W2, b2, out);
}

// round 8
// speedup vs baseline: 1.0611x; 1.0480x over previous
#include <cuda_runtime.h>
#include <cstdint>

#define BS   4
#define SEQ  128
#define DIM  768
#define HID  768
#define NOUT 2
#define MROWS (BS * SEQ)                    // 512
#define KSPLIT 384                          // K per split-K half

// ---------------- device scratch (no allocation allowed) -------------------
__device__ float g_ha[MROWS * HID];         // partial: a @ W1[:D], k-half 0
__device__ float g_hb[MROWS * HID];         // partial: b @ W1[D:] + b1, k-half 0
__device__ float g_ha2[MROWS * HID];        // partial k-half 1
__device__ float g_hb2[MROWS * HID];        // partial k-half 1

// ---------------------------------------------------------------------------
__device__ __forceinline__ uint32_t smem_u32(const void* p) {
    uint32_t a;
    asm("{ .reg .u64 t; cvta.to.shared.u64 t, %1; cvt.u32.u64 %0, t; }"
        : "=r"(a) : "l"(p));
    return a;
}

__device__ __forceinline__ void cp_async16(uint32_t saddr, const void* gptr) {
    asm volatile("cp.async.cg.shared.global [%0], [%1], 16;"
                 :: "r"(saddr), "l"(gptr) : "memory");
}
__device__ __forceinline__ void cp_commit() {
    asm volatile("cp.async.commit_group;" ::: "memory");
}
template <int N>
__device__ __forceinline__ void cp_wait() {
    asm volatile("cp.async.wait_group %0;" :: "n"(N) : "memory");
}

__device__ __forceinline__ uint32_t f2tf32(float x) {
    uint32_t u;
    asm("cvt.rna.tf32.f32 %0, %1;" : "=r"(u) : "f"(x));
    return u;
}

__device__ __forceinline__ void ldsm_x4(uint32_t* d, uint32_t saddr) {
    asm volatile(
        "ldmatrix.sync.aligned.m8n8.x4.shared.b16 {%0,%1,%2,%3}, [%4];"
        : "=r"(d[0]), "=r"(d[1]), "=r"(d[2]), "=r"(d[3]) : "r"(saddr));
}

__device__ __forceinline__ void mma_tf32(float* c, const uint32_t* a,
                                         const uint32_t* b) {
    asm volatile(
        "mma.sync.aligned.m16n8k8.row.col.f32.tf32.tf32.f32 "
        "{%0,%1,%2,%3}, {%4,%5,%6,%7}, {%8,%9}, {%0,%1,%2,%3};"
        : "+f"(c[0]), "+f"(c[1]), "+f"(c[2]), "+f"(c[3])
        : "r"(a[0]), "r"(a[1]), "r"(a[2]), "r"(a[3]), "r"(b[0]), "r"(b[1]));
}

// ---------------------------------------------------------------------------
// Kernel 1: projection GEMM via mma.sync tf32, split-K=2, BK=32.
// Reads raw fp32 inputs; RN-rounds to tf32 in registers (cvt.rna).
// A fragments via ldmatrix.x4 (1 LDSM = 4 LDS.32).
// CTA tile 64m x 64n, 128 threads = 4 warps (2x2), warp tile 32x32.
// 3-stage cp.async pipeline, prefetch issued before compute.
// Grid (12, 8, 4) = 384 CTAs. Dyn smem 55296 B.
// ---------------------------------------------------------------------------
#define ALD 36
#define BLD 72
#define STG_A (64 * ALD)
#define STG_B (32 * BLD)
#define PROJ_SMEM_BYTES (3 * (STG_A + STG_B) * 4)   // 55296

__global__ __launch_bounds__(128) void proj_tc(
    const float* __restrict__ a, const float* __restrict__ b,
    const float* __restrict__ W1, const float* __restrict__ b1)
{
    extern __shared__ float psm[];
    float* const Asm = psm;
    float* const Bsm = psm + 3 * STG_A;

    const int tid = threadIdx.x;
    const int wid = tid >> 5;
    const int lane = tid & 31;
    const int r = lane >> 2;            // 0..7
    const int c = lane & 3;             // 0..3
    const int wm = (wid >> 1) * 32;     // warp m base {0,32}
    const int wn = (wid & 1) * 32;      // warp n base {0,32}

    const int n0 = blockIdx.x * 64;
    const int m0 = blockIdx.y * 64;
    const int z  = blockIdx.z & 1;
    const int kh = blockIdx.z >> 1;
    const int kbase = kh * KSPLIT;

    const float* __restrict__ X = z ? b : a;
    const float* __restrict__ W = W1 + (size_t)z * DIM * HID;

    const uint32_t sA = smem_u32(Asm);
    const uint32_t sB = smem_u32(Bsm);

    // ldmatrix lane address (bytes within an A stage):
    // unit row = wm + (lane&7) + ((lane>>3)&1)*8,  col half = ((lane>>4)&1)*4
    const uint32_t a_lm0 =
        (uint32_t)(((wm + (lane & 7) + ((lane >> 3) & 1) * 8) * ALD
                    + ((lane >> 4) & 1) * 4) * 4);

    // per-chunk loads: A 64x32 = 512 f4 (4/thread), B 32x64 = 512 f4 (4/thread)
    auto ldchunk = [&](int chunk, int s) {
        const int k0 = kbase + chunk * 32;
        #pragma unroll
        for (int i = 0; i < 4; i++) {
            int f = i * 128 + tid;
            int row = f >> 3, kc = (f & 7) * 4;
            cp_async16(sA + (uint32_t)(s * STG_A + row * ALD + kc) * 4,
                       X + (size_t)(m0 + row) * DIM + k0 + kc);
        }
        #pragma unroll
        for (int i = 0; i < 4; i++) {
            int f = i * 128 + tid;
            int kr = f >> 4, nc = (f & 15) * 4;
            cp_async16(sB + (uint32_t)(s * STG_B + kr * BLD + nc) * 4,
                       W + (size_t)(k0 + kr) * HID + n0 + nc);
        }
        cp_commit();
    };

    float acc[2][4][4] = {};

    ldchunk(0, 0);
    ldchunk(1, 1);

    for (int chunk = 0; chunk < 12; chunk++) {
        const int s = chunk % 3;
        if (chunk < 11) cp_wait<1>(); else cp_wait<0>();
        __syncthreads();                       // publish stage s + WAR safety

        if (chunk + 2 < 12) ldchunk(chunk + 2, (chunk + 2) % 3);  // early issue

        const uint32_t aStage = sA + (uint32_t)(s * STG_A) * 4;
        const float* Bb = Bsm + s * STG_B;
        #pragma unroll
        for (int ks = 0; ks < 4; ks++) {
            const int kb = ks * 8;
            uint32_t af[2][4];
            #pragma unroll
            for (int mt = 0; mt < 2; mt++) {
                ldsm_x4(af[mt], aStage + a_lm0
                                + (uint32_t)(mt * 16 * ALD + kb) * 4);
                af[mt][0] = f2tf32(__uint_as_float(af[mt][0]));
                af[mt][1] = f2tf32(__uint_as_float(af[mt][1]));
                af[mt][2] = f2tf32(__uint_as_float(af[mt][2]));
                af[mt][3] = f2tf32(__uint_as_float(af[mt][3]));
            }
            uint32_t bf[4][2];
            #pragma unroll
            for (int nt = 0; nt < 4; nt++) {
                const float* bp = Bb + (kb + c) * BLD + wn + nt * 8 + r;
                bf[nt][0] = f2tf32(bp[0]);
                bf[nt][1] = f2tf32(bp[4 * BLD]);
            }
            #pragma unroll
            for (int nt = 0; nt < 4; nt++)
                #pragma unroll
                for (int mt = 0; mt < 2; mt++)
                    mma_tf32(acc[mt][nt], af[mt], bf[nt]);
        }
    }

    // epilogue: write per-split partial (+ b1 once, on z=1 k-half 0)
    float* __restrict__ outp = z ? (kh ? g_hb2 : g_hb) : (kh ? g_ha2 : g_ha);
    const bool addb = (z == 1) && (kh == 0);
    #pragma unroll
    for (int mt = 0; mt < 2; mt++) {
        #pragma unroll
        for (int nt = 0; nt < 4; nt++) {
            int m = m0 + wm + mt * 16 + r;
            int n = n0 + wn + nt * 8 + c * 2;
            float2 v0 = make_float2(acc[mt][nt][0], acc[mt][nt][1]);
            float2 v1 = make_float2(acc[mt][nt][2], acc[mt][nt][3]);
            if (addb) {
                float2 bb = *(const float2*)&b1[n];
                v0.x += bb.x; v0.y += bb.y;
                v1.x += bb.x; v1.y += bb.y;
            }
            *(float2*)&outp[(size_t)m * HID + n] = v0;
            *(float2*)&outp[(size_t)(m + 8) * HID + n] = v1;
        }
    }
}

// ---------------------------------------------------------------------------
// Kernel 2: pairwise relu + reduce to O=2, fused final output.
// Grid (8, 4, 4) = 128 CTAs, 256 threads = 2 h-half groups of 128.
// Sums the split-K proj partials during the smem fill.
// ---------------------------------------------------------------------------
#define HC 64
__global__ __launch_bounds__(256) void pair_kernel(
    const float* __restrict__ W2, const float* __restrict__ b2,
    float* __restrict__ out)
{
    const int tt = blockIdx.x;
    const int st = blockIdx.y;
    const int batch = blockIdx.z;

    __shared__ float sha[2][32][68];
    __shared__ float shB[2][16][65];
    __shared__ float sw[2][HC * 2];
    __shared__ float red[8][128];

    const int tid = threadIdx.x;
    const int g  = tid >> 7;
    const int lt = tid & 127;
    const int sq = lt >> 3;
    const int tq = lt & 7;
    const int h0base = g * (HID / 2);

    const size_t rowS = (size_t)(batch * SEQ + st * 32) * HID;
    const size_t rowT = (size_t)(batch * SEQ + tt * 16) * HID;
    const float* __restrict__ hap  = g_ha  + rowS;
    const float* __restrict__ hap2 = g_ha2 + rowS;
    const float* __restrict__ hbp  = g_hb  + rowT;
    const float* __restrict__ hbp2 = g_hb2 + rowT;

    float acc[2][2][2] = {};

    for (int hc = 0; hc < HID / 2; hc += HC) {
        const int h0 = h0base + hc;

        #pragma unroll
        for (int q = 0; q < 4; q++) {
            int f = q * 128 + lt;
            int row = f >> 4, col = (f & 15) * 4;
            float4 u  = *(const float4*)&hap [(size_t)row * HID + h0 + col];
            float4 u2 = *(const float4*)&hap2[(size_t)row * HID + h0 + col];
            u.x += u2.x; u.y += u2.y; u.z += u2.z; u.w += u2.w;
            *(float4*)&sha[g][row][col] = u;
        }
        #pragma unroll
        for (int q = 0; q < 2; q++) {
            int f = q * 128 + lt;
            int row = f >> 4, col = (f & 15) * 4;
            float4 v  = *(const float4*)&hbp [(size_t)row * HID + h0 + col];
            float4 v2 = *(const float4*)&hbp2[(size_t)row * HID + h0 + col];
            v.x += v2.x; v.y += v2.y; v.z += v2.z; v.w += v2.w;
            shB[g][row][col + 0] = v.x;
            shB[g][row][col + 1] = v.y;
            shB[g][row][col + 2] = v.z;
            shB[g][row][col + 3] = v.w;
        }
        if (lt < 32)
            *(float4*)&sw[g][lt * 4] = *(const float4*)&W2[h0 * 2 + lt * 4];
        __syncthreads();

        #pragma unroll 16
        for (int h = 0; h < HC; h++) {
            float a0 = sha[g][sq * 2][h];
            float a1 = sha[g][sq * 2 + 1][h];
            float b0 = shB[g][tq * 2][h];
            float b1v = shB[g][tq * 2 + 1][h];
            float2 wv = *(const float2*)&sw[g][2 * h];
            float r;
            r = fmaxf(a0 + b0,  0.f); acc[0][0][0] += r * wv.x; acc[0][0][1] += r * wv.y;
            r = fmaxf(a0 + b1v, 0.f); acc[0][1][0] += r * wv.x; acc[0][1][1] += r * wv.y;
            r = fmaxf(a1 + b0,  0.f); acc[1][0][0] += r * wv.x; acc[1][0][1] += r * wv.y;
            r = fmaxf(a1 + b1v, 0.f); acc[1][1][0] += r * wv.x; acc[1][1][1] += r * wv.y;
        }
        __syncthreads();
    }

    const float* af = (const float*)acc;
    if (g == 0) {
        #pragma unroll
        for (int k = 0; k < 8; k++) red[k][lt] = af[k];
    }
    __syncthreads();
    if (g == 1) {
        float c0 = b2[0], c1 = b2[1];
        #pragma unroll
        for (int i = 0; i < 2; i++) {
            int s = st * 32 + sq * 2 + i;
            int t = tt * 16 + tq * 2;
            float4 v;
            v.x = acc[i][0][0] + red[i * 4 + 0][lt] + c0;
            v.y = acc[i][0][1] + red[i * 4 + 1][lt] + c1;
            v.z = acc[i][1][0] + red[i * 4 + 2][lt] + c0;
            v.w = acc[i][1][1] + red[i * 4 + 3][lt] + c1;
            *(float4*)&out[(((size_t)batch * SEQ + s) * SEQ + t) * NOUT] = v;
        }
    }
}

// ---------------------------------------------------------------------------
extern "C" void kernel_launch(void* const* d_in, const int* in_sizes, int n_in,
                              void* d_out, int out_size)
{
    const float* a  = (const float*)d_in[0];
    const float* b  = (const float*)d_in[1];
    const float* W1 = (const float*)d_in[2];
    const float* b1 = (const float*)d_in[3];
    const float* W2 = (const float*)d_in[4];
    const float* b2 = (const float*)d_in[5];
    float* out = (float*)d_out;

    cudaFuncSetAttribute(proj_tc, cudaFuncAttributeMaxDynamicSharedMemorySize,
                         PROJ_SMEM_BYTES);

    proj_tc<<<dim3(HID / 64, MROWS / 64, 4), 128, PROJ_SMEM_BYTES>>>(a, b, W1, b1);
    pair_kernel<<<dim3(SEQ / 16, SEQ / 32, BS), 256>>>(W2, b2, out);
}

// round 10
// speedup vs baseline: 1.4057x; 1.3248x over previous
#include <cuda_runtime.h>
#include <cstdint>

#define BS   4
#define SEQ  128
#define DIM  768
#define HID  768
#define NOUT 2
#define MROWS (BS * SEQ)                    // 512
#define KSPLIT 384                          // K per split-K half

// ---------------- device scratch (no allocation allowed) -------------------
__device__ float g_ha[MROWS * HID];         // partial: a @ W1[:D], k-half 0
__device__ float g_hb[MROWS * HID];         // partial: b @ W1[D:] + b1, k-half 0
__device__ float g_ha2[MROWS * HID];        // partial k-half 1
__device__ float g_hb2[MROWS * HID];        // partial k-half 1

// ---------------------------------------------------------------------------
__device__ __forceinline__ uint32_t smem_u32(const void* p) {
    uint32_t a;
    asm("{ .reg .u64 t; cvta.to.shared.u64 t, %1; cvt.u32.u64 %0, t; }"
        : "=r"(a) : "l"(p));
    return a;
}

__device__ __forceinline__ void cp_async16(uint32_t saddr, const void* gptr) {
    asm volatile("cp.async.cg.shared.global [%0], [%1], 16;"
                 :: "r"(saddr), "l"(gptr) : "memory");
}
__device__ __forceinline__ void cp_commit() {
    asm volatile("cp.async.commit_group;" ::: "memory");
}
template <int N>
__device__ __forceinline__ void cp_wait() {
    asm volatile("cp.async.wait_group %0;" :: "n"(N) : "memory");
}

__device__ __forceinline__ uint32_t f2tf32(float x) {
    uint32_t u;
    asm("cvt.rna.tf32.f32 %0, %1;" : "=r"(u) : "f"(x));
    return u;
}

__device__ __forceinline__ void ldsm_x4(uint32_t* d, uint32_t saddr) {
    asm volatile(
        "ldmatrix.sync.aligned.m8n8.x4.shared.b16 {%0,%1,%2,%3}, [%4];"
        : "=r"(d[0]), "=r"(d[1]), "=r"(d[2]), "=r"(d[3]) : "r"(saddr));
}

__device__ __forceinline__ void mma_tf32(float* c, const uint32_t* a,
                                         const uint32_t* b) {
    asm volatile(
        "mma.sync.aligned.m16n8k8.row.col.f32.tf32.tf32.f32 "
        "{%0,%1,%2,%3}, {%4,%5,%6,%7}, {%8,%9}, {%0,%1,%2,%3};"
        : "+f"(c[0]), "+f"(c[1]), "+f"(c[2]), "+f"(c[3])
        : "r"(a[0]), "r"(a[1]), "r"(a[2]), "r"(a[3]), "r"(b[0]), "r"(b[1]));
}

// ---------------------------------------------------------------------------
// Kernel 1: projection GEMM (unchanged from R8 — proven ~10us).
// mma.sync tf32, split-K=2, BK=32, ldmatrix A fragments, in-reg cvt.rna.
// CTA tile 64x64, 128 threads, warp tile 32x32, 3-stage cp.async.
// Grid (12, 8, 4) = 384 CTAs. Dyn smem 55296 B.
// ---------------------------------------------------------------------------
#define ALD 36
#define BLD 72
#define STG_A (64 * ALD)
#define STG_B (32 * BLD)
#define PROJ_SMEM_BYTES (3 * (STG_A + STG_B) * 4)   // 55296

__global__ __launch_bounds__(128) void proj_tc(
    const float* __restrict__ a, const float* __restrict__ b,
    const float* __restrict__ W1, const float* __restrict__ b1)
{
    extern __shared__ float psm[];
    float* const Asm = psm;
    float* const Bsm = psm + 3 * STG_A;

    const int tid = threadIdx.x;
    const int wid = tid >> 5;
    const int lane = tid & 31;
    const int r = lane >> 2;
    const int c = lane & 3;
    const int wm = (wid >> 1) * 32;
    const int wn = (wid & 1) * 32;

    const int n0 = blockIdx.x * 64;
    const int m0 = blockIdx.y * 64;
    const int z  = blockIdx.z & 1;
    const int kh = blockIdx.z >> 1;
    const int kbase = kh * KSPLIT;

    const float* __restrict__ X = z ? b : a;
    const float* __restrict__ W = W1 + (size_t)z * DIM * HID;

    const uint32_t sA = smem_u32(Asm);
    const uint32_t sB = smem_u32(Bsm);

    const uint32_t a_lm0 =
        (uint32_t)(((wm + (lane & 7) + ((lane >> 3) & 1) * 8) * ALD
                    + ((lane >> 4) & 1) * 4) * 4);

    auto ldchunk = [&](int chunk, int s) {
        const int k0 = kbase + chunk * 32;
        #pragma unroll
        for (int i = 0; i < 4; i++) {
            int f = i * 128 + tid;
            int row = f >> 3, kc = (f & 7) * 4;
            cp_async16(sA + (uint32_t)(s * STG_A + row * ALD + kc) * 4,
                       X + (size_t)(m0 + row) * DIM + k0 + kc);
        }
        #pragma unroll
        for (int i = 0; i < 4; i++) {
            int f = i * 128 + tid;
            int kr = f >> 4, nc = (f & 15) * 4;
            cp_async16(sB + (uint32_t)(s * STG_B + kr * BLD + nc) * 4,
                       W + (size_t)(k0 + kr) * HID + n0 + nc);
        }
        cp_commit();
    };

    float acc[2][4][4] = {};

    ldchunk(0, 0);
    ldchunk(1, 1);

    for (int chunk = 0; chunk < 12; chunk++) {
        const int s = chunk % 3;
        if (chunk < 11) cp_wait<1>(); else cp_wait<0>();
        __syncthreads();

        if (chunk + 2 < 12) ldchunk(chunk + 2, (chunk + 2) % 3);

        const uint32_t aStage = sA + (uint32_t)(s * STG_A) * 4;
        const float* Bb = Bsm + s * STG_B;
        #pragma unroll
        for (int ks = 0; ks < 4; ks++) {
            const int kb = ks * 8;
            uint32_t af[2][4];
            #pragma unroll
            for (int mt = 0; mt < 2; mt++) {
                ldsm_x4(af[mt], aStage + a_lm0
                                + (uint32_t)(mt * 16 * ALD + kb) * 4);
                af[mt][0] = f2tf32(__uint_as_float(af[mt][0]));
                af[mt][1] = f2tf32(__uint_as_float(af[mt][1]));
                af[mt][2] = f2tf32(__uint_as_float(af[mt][2]));
                af[mt][3] = f2tf32(__uint_as_float(af[mt][3]));
            }
            uint32_t bf[4][2];
            #pragma unroll
            for (int nt = 0; nt < 4; nt++) {
                const float* bp = Bb + (kb + c) * BLD + wn + nt * 8 + r;
                bf[nt][0] = f2tf32(bp[0]);
                bf[nt][1] = f2tf32(bp[4 * BLD]);
            }
            #pragma unroll
            for (int nt = 0; nt < 4; nt++)
                #pragma unroll
                for (int mt = 0; mt < 2; mt++)
                    mma_tf32(acc[mt][nt], af[mt], bf[nt]);
        }
    }

    float* __restrict__ outp = z ? (kh ? g_hb2 : g_hb) : (kh ? g_ha2 : g_ha);
    const bool addb = (z == 1) && (kh == 0);
    #pragma unroll
    for (int mt = 0; mt < 2; mt++) {
        #pragma unroll
        for (int nt = 0; nt < 4; nt++) {
            int m = m0 + wm + mt * 16 + r;
            int n = n0 + wn + nt * 8 + c * 2;
            float2 v0 = make_float2(acc[mt][nt][0], acc[mt][nt][1]);
            float2 v1 = make_float2(acc[mt][nt][2], acc[mt][nt][3]);
            if (addb) {
                float2 bb = *(const float2*)&b1[n];
                v0.x += bb.x; v0.y += bb.y;
                v1.x += bb.x; v1.y += bb.y;
            }
            *(float2*)&outp[(size_t)m * HID + n] = v0;
            *(float2*)&outp[(size_t)(m + 8) * HID + n] = v1;
        }
    }
}

// ---------------------------------------------------------------------------
// Kernel 2 (REWRITTEN): pairwise relu + reduce to O=2.
// Tile 16s x 16t per CTA, grid (8, 8, 4) = 256 CTAs.
// 256 threads = 4 H-groups of 64 (192 h each, chunked by 64).
// Each thread: 4 pairs (s in {sq, sq+8}, t in {tq, tq+8}), h vectorized x4
// via LDS.128. Groups reduced via smem; group 0 adds b2, writes final out.
// ---------------------------------------------------------------------------
#define HC 64
__global__ __launch_bounds__(256) void pair_kernel(
    const float* __restrict__ W2, const float* __restrict__ b2,
    float* __restrict__ out)
{
    const int tt = blockIdx.x;              // t tile (16)
    const int st = blockIdx.y;              // s tile (16)
    const int batch = blockIdx.z;

    __shared__ float sha[4][16][68];        // [g][s][h]
    __shared__ float shB[4][16][68];        // [g][t][h]
    __shared__ float sw[4][2 * HC];         // [g][(o0,o1) per h]
    __shared__ float red[3][8][64];

    const int tid = threadIdx.x;
    const int g  = tid >> 6;                // 0..3
    const int lt = tid & 63;
    const int sq = lt >> 3;                 // 0..7
    const int tq = lt & 7;                  // 0..7

    const size_t rowS = (size_t)(batch * SEQ + st * 16) * HID;
    const size_t rowT = (size_t)(batch * SEQ + tt * 16) * HID;
    const float* __restrict__ hap  = g_ha  + rowS;
    const float* __restrict__ hap2 = g_ha2 + rowS;
    const float* __restrict__ hbp  = g_hb  + rowT;
    const float* __restrict__ hbp2 = g_hb2 + rowT;

    float acc[2][2][2] = {};                // [s-half][t-half][o]

    #pragma unroll 1
    for (int hc = 0; hc < 192; hc += HC) {
        const int h0 = g * 192 + hc;

        // fill sha / shB: 16 rows x 64 h each = 256 f4, 4 per thread
        #pragma unroll
        for (int q = 0; q < 4; q++) {
            int f = q * 64 + lt;
            int row = f >> 4, col = (f & 15) * 4;
            float4 u  = *(const float4*)&hap [(size_t)row * HID + h0 + col];
            float4 u2 = *(const float4*)&hap2[(size_t)row * HID + h0 + col];
            u.x += u2.x; u.y += u2.y; u.z += u2.z; u.w += u2.w;
            *(float4*)&sha[g][row][col] = u;
            float4 v  = *(const float4*)&hbp [(size_t)row * HID + h0 + col];
            float4 v2 = *(const float4*)&hbp2[(size_t)row * HID + h0 + col];
            v.x += v2.x; v.y += v2.y; v.z += v2.z; v.w += v2.w;
            *(float4*)&shB[g][row][col] = v;
        }
        if (lt < 32)
            *(float4*)&sw[g][lt * 4] = *(const float4*)&W2[h0 * 2 + lt * 4];
        __syncthreads();

        #pragma unroll
        for (int h = 0; h < HC; h += 4) {
            float4 A0 = *(const float4*)&sha[g][sq][h];
            float4 A1 = *(const float4*)&sha[g][sq + 8][h];
            float4 B0 = *(const float4*)&shB[g][tq][h];
            float4 B1 = *(const float4*)&shB[g][tq + 8][h];
            float4 W0 = *(const float4*)&sw[g][2 * h];
            float4 W1 = *(const float4*)&sw[g][2 * h + 4];
            float r;
            // h+0 (w = W0.x, W0.y)
            r = fmaxf(A0.x + B0.x, 0.f); acc[0][0][0] += r * W0.x; acc[0][0][1] += r * W0.y;
            r = fmaxf(A0.x + B1.x, 0.f); acc[0][1][0] += r * W0.x; acc[0][1][1] += r * W0.y;
            r = fmaxf(A1.x + B0.x, 0.f); acc[1][0][0] += r * W0.x; acc[1][0][1] += r * W0.y;
            r = fmaxf(A1.x + B1.x, 0.f); acc[1][1][0] += r * W0.x; acc[1][1][1] += r * W0.y;
            // h+1 (w = W0.z, W0.w)
            r = fmaxf(A0.y + B0.y, 0.f); acc[0][0][0] += r * W0.z; acc[0][0][1] += r * W0.w;
            r = fmaxf(A0.y + B1.y, 0.f); acc[0][1][0] += r * W0.z; acc[0][1][1] += r * W0.w;
            r = fmaxf(A1.y + B0.y, 0.f); acc[1][0][0] += r * W0.z; acc[1][0][1] += r * W0.w;
            r = fmaxf(A1.y + B1.y, 0.f); acc[1][1][0] += r * W0.z; acc[1][1][1] += r * W0.w;
            // h+2 (w = W1.x, W1.y)
            r = fmaxf(A0.z + B0.z, 0.f); acc[0][0][0] += r * W1.x; acc[0][0][1] += r * W1.y;
            r = fmaxf(A0.z + B1.z, 0.f); acc[0][1][0] += r * W1.x; acc[0][1][1] += r * W1.y;
            r = fmaxf(A1.z + B0.z, 0.f); acc[1][0][0] += r * W1.x; acc[1][0][1] += r * W1.y;
            r = fmaxf(A1.z + B1.z, 0.f); acc[1][1][0] += r * W1.x; acc[1][1][1] += r * W1.y;
            // h+3 (w = W1.z, W1.w)
            r = fmaxf(A0.w + B0.w, 0.f); acc[0][0][0] += r * W1.z; acc[0][0][1] += r * W1.w;
            r = fmaxf(A0.w + B1.w, 0.f); acc[0][1][0] += r * W1.z; acc[0][1][1] += r * W1.w;
            r = fmaxf(A1.w + B0.w, 0.f); acc[1][0][0] += r * W1.z; acc[1][0][1] += r * W1.w;
            r = fmaxf(A1.w + B1.w, 0.f); acc[1][1][0] += r * W1.z; acc[1][1][1] += r * W1.w;
        }
        __syncthreads();
    }

    // cross-group reduction: groups 1-3 publish, group 0 combines + writes
    const float* af = (const float*)acc;
    if (g) {
        #pragma unroll
        for (int k = 0; k < 8; k++) red[g - 1][k][lt] = af[k];
    }
    __syncthreads();
    if (g == 0) {
        const float c0 = b2[0], c1 = b2[1];
        #pragma unroll
        for (int i = 0; i < 2; i++) {
            #pragma unroll
            for (int j = 0; j < 2; j++) {
                int k0i = i * 4 + j * 2;
                float v0 = acc[i][j][0] + red[0][k0i][lt] + red[1][k0i][lt]
                         + red[2][k0i][lt] + c0;
                float v1 = acc[i][j][1] + red[0][k0i + 1][lt] + red[1][k0i + 1][lt]
                         + red[2][k0i + 1][lt] + c1;
                int s = st * 16 + sq + i * 8;
                int t = tt * 16 + tq + j * 8;
                *(float2*)&out[(((size_t)batch * SEQ + s) * SEQ + t) * NOUT]
                    = make_float2(v0, v1);
            }
        }
    }
}

// ---------------------------------------------------------------------------
extern "C" void kernel_launch(void* const* d_in, const int* in_sizes, int n_in,
                              void* d_out, int out_size)
{
    const float* a  = (const float*)d_in[0];
    const float* b  = (const float*)d_in[1];
    const float* W1 = (const float*)d_in[2];
    const float* b1 = (const float*)d_in[3];
    const float* W2 = (const float*)d_in[4];
    const float* b2 = (const float*)d_in[5];
    float* out = (float*)d_out;

    cudaFuncSetAttribute(proj_tc, cudaFuncAttributeMaxDynamicSharedMemorySize,
                         PROJ_SMEM_BYTES);

    proj_tc<<<dim3(HID / 64, MROWS / 64, 4), 128, PROJ_SMEM_BYTES>>>(a, b, W1, b1);
    pair_kernel<<<dim3(SEQ / 16, SEQ / 16, BS), 256>>>(W2, b2, out);
}